// round 1
// baseline (speedup 1.0000x reference)
#include <cuda_runtime.h>
#include <math.h>

// Problem dims (fixed by the reference)
#define NTOK 4096
#define DIM  1024

// ---------------- scratch (no allocations allowed) ----------------
__device__ float g_K[(size_t)NTOK * DIM];
__device__ float g_Q[(size_t)NTOK * DIM];
__device__ float g_V[(size_t)NTOK * DIM];
__device__ float g_S[(size_t)NTOK * NTOK];   // scores -> attn (in place)
__device__ float g_O[(size_t)NTOK * DIM];    // attn @ V

// ---------------- SGEMM: C = A * op(B) (+ bias) --------------------
// A: [M,K] row-major. TRANSB=false: B [K,N] row-major. TRANSB=true: B [N,K] row-major (C = A*B^T).
// 128x128 block tile, BK=16, 256 threads, 8x8 per-thread microtile.
// Requires M,N % 128 == 0 and K % 16 == 0 (true for all calls here).
template<bool TRANSB, bool BIAS>
__global__ __launch_bounds__(256)
void sgemm_kernel(const float* __restrict__ A,
                  const float* __restrict__ B,
                  const float* __restrict__ bias,
                  float* __restrict__ C,
                  int M, int N, int K)
{
    __shared__ float As[16][132];   // [k][m], padded to dodge bank conflicts
    __shared__ float Bs[16][132];   // [k][n]

    const int tid  = threadIdx.x;
    const int brow = blockIdx.y * 128;   // M offset
    const int bcol = blockIdx.x * 128;   // N offset

    const int tr = tid >> 4;             // 0..15  -> rows tr*8..tr*8+7
    const int tc = tid & 15;             // 0..15  -> cols tc*8..tc*8+7

    // loader indices (float4 along K for A / B^T, along N for B)
    const int l_r  = tid >> 2;           // 0..63
    const int l_c4 = (tid & 3) * 4;      // 0,4,8,12

    float acc[8][8];
    #pragma unroll
    for (int i = 0; i < 8; i++)
        #pragma unroll
        for (int j = 0; j < 8; j++) acc[i][j] = 0.f;

    for (int k0 = 0; k0 < K; k0 += 16) {
        // ---- load A tile (128x16), store transposed As[k][m]
        #pragma unroll
        for (int i = 0; i < 2; i++) {
            int m = l_r + i * 64;
            float4 v = *(const float4*)&A[(size_t)(brow + m) * K + k0 + l_c4];
            As[l_c4 + 0][m] = v.x;
            As[l_c4 + 1][m] = v.y;
            As[l_c4 + 2][m] = v.z;
            As[l_c4 + 3][m] = v.w;
        }
        // ---- load B tile -> Bs[k][n]
        if (TRANSB) {
            #pragma unroll
            for (int i = 0; i < 2; i++) {
                int n = l_r + i * 64;
                float4 v = *(const float4*)&B[(size_t)(bcol + n) * K + k0 + l_c4];
                Bs[l_c4 + 0][n] = v.x;
                Bs[l_c4 + 1][n] = v.y;
                Bs[l_c4 + 2][n] = v.z;
                Bs[l_c4 + 3][n] = v.w;
            }
        } else {
            int b_r  = tid >> 5;          // 0..7
            int b_c4 = (tid & 31) * 4;    // 0..124
            #pragma unroll
            for (int i = 0; i < 2; i++) {
                int kk = b_r + i * 8;
                float4 v = *(const float4*)&B[(size_t)(k0 + kk) * N + bcol + b_c4];
                *(float4*)&Bs[kk][b_c4] = v;
            }
        }
        __syncthreads();

        #pragma unroll
        for (int kk = 0; kk < 16; kk++) {
            float4 a0 = *(const float4*)&As[kk][tr * 8];
            float4 a1 = *(const float4*)&As[kk][tr * 8 + 4];
            float4 b0 = *(const float4*)&Bs[kk][tc * 8];
            float4 b1 = *(const float4*)&Bs[kk][tc * 8 + 4];
            float a[8] = {a0.x, a0.y, a0.z, a0.w, a1.x, a1.y, a1.z, a1.w};
            float b[8] = {b0.x, b0.y, b0.z, b0.w, b1.x, b1.y, b1.z, b1.w};
            #pragma unroll
            for (int i = 0; i < 8; i++)
                #pragma unroll
                for (int j = 0; j < 8; j++)
                    acc[i][j] = fmaf(a[i], b[j], acc[i][j]);
        }
        __syncthreads();
    }

    float bj[8];
    #pragma unroll
    for (int j = 0; j < 8; j++)
        bj[j] = BIAS ? bias[bcol + tc * 8 + j] : 0.f;

    #pragma unroll
    for (int i = 0; i < 8; i++) {
        int m = brow + tr * 8 + i;
        #pragma unroll
        for (int j = 0; j < 8; j += 4) {
            float4 v;
            v.x = acc[i][j + 0] + bj[j + 0];
            v.y = acc[i][j + 1] + bj[j + 1];
            v.z = acc[i][j + 2] + bj[j + 2];
            v.w = acc[i][j + 3] + bj[j + 3];
            *(float4*)&C[(size_t)m * N + bcol + tc * 8 + j] = v;
        }
    }
}

// ---------------- row softmax (in place), 4096 cols, 256 threads ----
__global__ __launch_bounds__(256)
void softmax_rows(float* __restrict__ S)
{
    const int row = blockIdx.x;
    float* p = S + (size_t)row * NTOK;
    const int tid = threadIdx.x;

    float vals[16];
    float mx = -INFINITY;
    #pragma unroll
    for (int i = 0; i < 16; i++) {
        vals[i] = p[tid + i * 256];
        mx = fmaxf(mx, vals[i]);
    }

    __shared__ float red[8];
    #pragma unroll
    for (int o = 16; o; o >>= 1) mx = fmaxf(mx, __shfl_xor_sync(0xffffffffu, mx, o));
    if ((tid & 31) == 0) red[tid >> 5] = mx;
    __syncthreads();
    mx = red[0];
    #pragma unroll
    for (int i = 1; i < 8; i++) mx = fmaxf(mx, red[i]);
    __syncthreads();

    float s = 0.f;
    #pragma unroll
    for (int i = 0; i < 16; i++) {
        vals[i] = __expf(vals[i] - mx);
        s += vals[i];
    }
    #pragma unroll
    for (int o = 16; o; o >>= 1) s += __shfl_xor_sync(0xffffffffu, s, o);
    if ((tid & 31) == 0) red[tid >> 5] = s;
    __syncthreads();
    s = red[0];
    #pragma unroll
    for (int i = 1; i < 8; i++) s += red[i];

    float inv = 1.f / s;
    #pragma unroll
    for (int i = 0; i < 16; i++) p[tid + i * 256] = vals[i] * inv;
}

// ---------------- residual + LayerNorm, row of 1024, 256 threads ----
__global__ __launch_bounds__(256)
void residual_ln(const float* __restrict__ O, const float* __restrict__ X,
                 const float* __restrict__ gamma, const float* __restrict__ beta,
                 float* __restrict__ out)
{
    const int row = blockIdx.x;
    const int tid = threadIdx.x;
    const float* o = O + (size_t)row * DIM;
    const float* x = X + (size_t)row * DIM;

    float v[4];
    float s = 0.f;
    #pragma unroll
    for (int i = 0; i < 4; i++) {
        int c = tid + i * 256;
        v[i] = o[c] + x[c];
        s += v[i];
    }

    __shared__ float red[8];
    #pragma unroll
    for (int off = 16; off; off >>= 1) s += __shfl_xor_sync(0xffffffffu, s, off);
    if ((tid & 31) == 0) red[tid >> 5] = s;
    __syncthreads();
    s = red[0];
    #pragma unroll
    for (int i = 1; i < 8; i++) s += red[i];
    const float mu = s * (1.f / DIM);
    __syncthreads();

    float vs = 0.f;
    #pragma unroll
    for (int i = 0; i < 4; i++) {
        float d = v[i] - mu;
        vs += d * d;
    }
    #pragma unroll
    for (int off = 16; off; off >>= 1) vs += __shfl_xor_sync(0xffffffffu, vs, off);
    if ((tid & 31) == 0) red[tid >> 5] = vs;
    __syncthreads();
    vs = red[0];
    #pragma unroll
    for (int i = 1; i < 8; i++) vs += red[i];
    const float r = rsqrtf(vs * (1.f / DIM) + 1e-5f);

    #pragma unroll
    for (int i = 0; i < 4; i++) {
        int c = tid + i * 256;
        out[(size_t)row * DIM + c] = (v[i] - mu) * r * gamma[c] + beta[c];
    }
}

// ---------------- launch -------------------------------------------
extern "C" void kernel_launch(void* const* d_in, const int* in_sizes, int n_in,
                              void* d_out, int out_size)
{
    const float* X     = (const float*)d_in[0];
    const float* Wk    = (const float*)d_in[1];
    const float* bk    = (const float*)d_in[2];
    const float* Wq    = (const float*)d_in[3];
    const float* bq    = (const float*)d_in[4];
    const float* Wv    = (const float*)d_in[5];
    const float* bv    = (const float*)d_in[6];
    const float* gamma = (const float*)d_in[7];
    const float* beta  = (const float*)d_in[8];
    float* out = (float*)d_out;

    float *pK, *pQ, *pV, *pS, *pO;
    cudaGetSymbolAddress((void**)&pK, g_K);
    cudaGetSymbolAddress((void**)&pQ, g_Q);
    cudaGetSymbolAddress((void**)&pV, g_V);
    cudaGetSymbolAddress((void**)&pS, g_S);
    cudaGetSymbolAddress((void**)&pO, g_O);

    dim3 blk(256);

    // projections: [4096,1024] = X[4096,1024] @ W[1024,1024] + b
    dim3 gProj(DIM / 128, NTOK / 128);
    sgemm_kernel<false, true><<<gProj, blk>>>(X, Wk, bk, pK, NTOK, DIM, DIM);
    sgemm_kernel<false, true><<<gProj, blk>>>(X, Wq, bq, pQ, NTOK, DIM, DIM);
    sgemm_kernel<false, true><<<gProj, blk>>>(X, Wv, bv, pV, NTOK, DIM, DIM);

    // scores: S[n,m] = sum_k K[n,k] * Q[m,k]  -> A=K, B=Q, TRANSB
    dim3 gScore(NTOK / 128, NTOK / 128);
    sgemm_kernel<true, false><<<gScore, blk>>>(pK, pQ, nullptr, pS, NTOK, NTOK, DIM);

    // softmax rows in place
    softmax_rows<<<NTOK, blk>>>(pS);

    // O = attn @ V : [4096,1024]
    sgemm_kernel<false, false><<<gProj, blk>>>(pS, pV, nullptr, pO, NTOK, DIM, NTOK);

    // residual + LN
    residual_ln<<<NTOK, blk>>>(pO, X, gamma, beta, out);
}

// round 6
// speedup vs baseline: 2.1876x; 2.1876x over previous
#include <cuda_runtime.h>
#include <cuda_bf16.h>
#include <cstdint>
#include <math.h>

#define NTOK 4096
#define DIM  1024
typedef __nv_bfloat16 bf16;

// ------------------------------------------------------------------
// helpers
// ------------------------------------------------------------------
__device__ __forceinline__ uint32_t smem_to_u32(const void* p) {
    uint32_t a;
    asm("{ .reg .u64 t; cvta.to.shared.u64 t, %1; cvt.u32.u64 %0, t; }" : "=r"(a) : "l"(p));
    return a;
}
__device__ __forceinline__ void cp16(uint32_t s, const void* g) {
    asm volatile("cp.async.cg.shared.global [%0], [%1], 16;" :: "r"(s), "l"(g));
}
__device__ __forceinline__ void ldsm4(uint32_t* r, uint32_t addr) {
    asm volatile("ldmatrix.sync.aligned.m8n8.x4.shared.b16 {%0,%1,%2,%3}, [%4];"
                 : "=r"(r[0]), "=r"(r[1]), "=r"(r[2]), "=r"(r[3]) : "r"(addr));
}
__device__ __forceinline__ void mma_bf16(float* c, const uint32_t* a, const uint32_t* b) {
    asm volatile("mma.sync.aligned.m16n8k16.row.col.f32.bf16.bf16.f32 "
                 "{%0,%1,%2,%3}, {%4,%5,%6,%7}, {%8,%9}, {%0,%1,%2,%3};"
                 : "+f"(c[0]), "+f"(c[1]), "+f"(c[2]), "+f"(c[3])
                 : "r"(a[0]), "r"(a[1]), "r"(a[2]), "r"(a[3]), "r"(b[0]), "r"(b[1]));
}
__device__ __forceinline__ uint32_t pack2(bf16 a, bf16 b) {
    __nv_bfloat162 t(a, b);
    return *(uint32_t*)&t;
}

// ------------------------------------------------------------------
// scratch (no allocations allowed)
// ------------------------------------------------------------------
__device__ bf16 g_Xh[NTOK * DIM], g_Xl[NTOK * DIM];
__device__ bf16 g_Wkt_h[DIM * DIM], g_Wkt_l[DIM * DIM];
__device__ bf16 g_Wqt_h[DIM * DIM], g_Wqt_l[DIM * DIM];
__device__ bf16 g_Wvt_h[DIM * DIM], g_Wvt_l[DIM * DIM];
__device__ bf16 g_Kh[NTOK * DIM], g_Kl[NTOK * DIM];
__device__ bf16 g_Qh[NTOK * DIM], g_Ql[NTOK * DIM];
__device__ bf16 g_Vth[DIM * NTOK], g_Vtl[DIM * NTOK];
__device__ float g_S[(size_t)NTOK * NTOK];
__device__ bf16 g_Ph[(size_t)NTOK * NTOK], g_Pl[(size_t)NTOK * NTOK];
__device__ float g_O[NTOK * DIM];

// ------------------------------------------------------------------
// fp32 -> bf16 hi/lo split
// ------------------------------------------------------------------
__global__ __launch_bounds__(256) void split_kernel(const float* __restrict__ src,
                                                    bf16* __restrict__ h, bf16* __restrict__ l, int n4)
{
    int i = blockIdx.x * 256 + threadIdx.x;
    if (i >= n4) return;
    float4 v = ((const float4*)src)[i];
    bf16 h0 = __float2bfloat16(v.x), h1 = __float2bfloat16(v.y);
    bf16 h2 = __float2bfloat16(v.z), h3 = __float2bfloat16(v.w);
    bf16 l0 = __float2bfloat16(v.x - __bfloat162float(h0));
    bf16 l1 = __float2bfloat16(v.y - __bfloat162float(h1));
    bf16 l2 = __float2bfloat16(v.z - __bfloat162float(h2));
    bf16 l3 = __float2bfloat16(v.w - __bfloat162float(h3));
    ((uint2*)h)[i] = make_uint2(pack2(h0, h1), pack2(h2, h3));
    ((uint2*)l)[i] = make_uint2(pack2(l0, l1), pack2(l2, l3));
}

// W [K,N] row-major -> Wt hi/lo [N,K]
__global__ __launch_bounds__(256) void transpose_split_kernel(const float* __restrict__ W,
                                                              bf16* __restrict__ Th, bf16* __restrict__ Tl)
{
    __shared__ float t[32][33];
    int tx = threadIdx.x & 31, ty = threadIdx.x >> 5;
    int n0 = blockIdx.x * 32, k0 = blockIdx.y * 32;
    #pragma unroll
    for (int j = 0; j < 32; j += 8)
        t[ty + j][tx] = W[(size_t)(k0 + ty + j) * DIM + n0 + tx];
    __syncthreads();
    #pragma unroll
    for (int j = 0; j < 32; j += 8) {
        float v = t[tx][ty + j];
        bf16 h = __float2bfloat16(v);
        bf16 l = __float2bfloat16(v - __bfloat162float(h));
        size_t o = (size_t)(n0 + ty + j) * DIM + k0 + tx;
        Th[o] = h;
        Tl[o] = l;
    }
}

// ------------------------------------------------------------------
// bf16x3 emulated fp32 GEMM on mma.sync:
//   C[M,N] = A[M,K] @ B[N,K]^T (+ bias),  A/B as hi/lo bf16 pairs (K-major).
// CTA 128x128, BK=32, 8 warps (2x4), warp tile 64x32, double-buffered cp.async.
// Both A and B fragments use non-trans ldmatrix (K-major smem rows).
// ------------------------------------------------------------------
#define BM 128
#define BN 128
#define BK 32
#define LDS_ROW 40                       // bf16 elems per smem row (32 + 8 pad)
#define LDS_ROWB (LDS_ROW * 2)           // 80 bytes
#define MAT_BYTES (BM * LDS_ROWB)        // 10240
#define STAGE_BYTES (4 * MAT_BYTES)      // Ah, Al, Bh, Bl
#define GEMM_SMEM (2 * STAGE_BYTES)      // 81920

#define AH_OFF 0
#define AL_OFF MAT_BYTES
#define BH_OFF (2 * MAT_BYTES)
#define BL_OFF (3 * MAT_BYTES)

__device__ __forceinline__ void load_chunk(uint32_t stage,
    const bf16* __restrict__ Ah, const bf16* __restrict__ Al,
    const bf16* __restrict__ Bh, const bf16* __restrict__ Bl,
    int brow, int bcol, int K, int k0, int tid)
{
    // each matrix: 128 rows x 32 cols bf16 = 128 x 4 chunks of 16B
    #pragma unroll
    for (int it = 0; it < 2; it++) {
        int idx = tid + it * 256;        // 0..511
        int r = idx >> 2, c = idx & 3;
        uint32_t so = (uint32_t)(r * LDS_ROWB + c * 16);
        size_t goA = (size_t)(brow + r) * K + k0 + c * 8;
        size_t goB = (size_t)(bcol + r) * K + k0 + c * 8;
        cp16(stage + AH_OFF + so, Ah + goA);
        cp16(stage + AL_OFF + so, Al + goA);
        cp16(stage + BH_OFF + so, Bh + goB);
        cp16(stage + BL_OFF + so, Bl + goB);
    }
    asm volatile("cp.async.commit_group;" ::: "memory");
}

// BIAS_MODE: 0 none, 1 per-col, 2 per-row.  OUT_SPLIT: 0 fp32 C, 1 hi/lo bf16 C.
template<int BIAS_MODE, int OUT_SPLIT>
__global__ __launch_bounds__(256, 1) void gemm3_kernel(
    const bf16* __restrict__ Ah, const bf16* __restrict__ Al,
    const bf16* __restrict__ Bh, const bf16* __restrict__ Bl,
    const float* __restrict__ bias,
    float* __restrict__ Cf, bf16* __restrict__ Ch, bf16* __restrict__ Cl,
    int N, int K)
{
    extern __shared__ char smem[];
    const uint32_t sb = smem_to_u32(smem);
    const int tid = threadIdx.x, wid = tid >> 5, lid = tid & 31;
    const int wm = wid >> 2, wn = wid & 3;            // warp grid 2 x 4
    const int brow = blockIdx.y * BM, bcol = blockIdx.x * BN;

    // ldmatrix lane addressing (non-trans for both operands, K-major rows)
    const int lt = lid >> 3, lr = lid & 7;
    const int a_row = (lt & 1) * 8 + lr, a_col = (lt >> 1) * 8;   // A: m-tiles x k-halves
    const int b_row = (lt >> 1) * 8 + lr, b_col = (lt & 1) * 8;   // B: n-tiles x k-halves

    float acc[4][4][4];
    #pragma unroll
    for (int i = 0; i < 4; i++)
        #pragma unroll
        for (int j = 0; j < 4; j++)
            #pragma unroll
            for (int k = 0; k < 4; k++) acc[i][j][k] = 0.f;

    const int nch = K / BK;
    load_chunk(sb, Ah, Al, Bh, Bl, brow, bcol, K, 0, tid);
    load_chunk(sb + STAGE_BYTES, Ah, Al, Bh, Bl, brow, bcol, K, BK, tid);

    for (int i = 0; i < nch; i++) {
        const uint32_t st = sb + (i & 1) * STAGE_BYTES;
        if (i < nch - 1) asm volatile("cp.async.wait_group 1;" ::: "memory");
        else             asm volatile("cp.async.wait_group 0;" ::: "memory");
        __syncthreads();

        #pragma unroll
        for (int ks = 0; ks < 2; ks++) {
            const uint32_t cb = (uint32_t)((ks * 16) * 2);
            uint32_t ah[4][4], al[4][4], bh[2][4], bl[2][4];
            #pragma unroll
            for (int mi = 0; mi < 4; mi++) {
                uint32_t ro = (uint32_t)((wm * 64 + mi * 16 + a_row) * LDS_ROWB) + cb + a_col * 2;
                ldsm4(ah[mi], st + AH_OFF + ro);
                ldsm4(al[mi], st + AL_OFF + ro);
            }
            #pragma unroll
            for (int nj = 0; nj < 2; nj++) {
                uint32_t ro = (uint32_t)((wn * 32 + nj * 16 + b_row) * LDS_ROWB) + cb + b_col * 2;
                ldsm4(bh[nj], st + BH_OFF + ro);
                ldsm4(bl[nj], st + BL_OFF + ro);
            }
            #pragma unroll
            for (int mi = 0; mi < 4; mi++)
                #pragma unroll
                for (int ni = 0; ni < 4; ni++) {
                    const uint32_t* ph = &bh[ni >> 1][(ni & 1) * 2];
                    const uint32_t* pl = &bl[ni >> 1][(ni & 1) * 2];
                    mma_bf16(acc[mi][ni], ah[mi], ph);
                    mma_bf16(acc[mi][ni], ah[mi], pl);
                    mma_bf16(acc[mi][ni], al[mi], ph);
                }
        }
        __syncthreads();
        if (i + 2 < nch)
            load_chunk(st, Ah, Al, Bh, Bl, brow, bcol, K, (i + 2) * BK, tid);
    }

    // ---------------- epilogue ----------------
    const int g = lid >> 2, t2 = (lid & 3) * 2;
    #pragma unroll
    for (int mi = 0; mi < 4; mi++) {
        #pragma unroll
        for (int ni = 0; ni < 4; ni++) {
            float* c = acc[mi][ni];
            int r0 = brow + wm * 64 + mi * 16 + g;
            int r1 = r0 + 8;
            int col = bcol + wn * 32 + ni * 8 + t2;
            float v0 = c[0], v1 = c[1], v2 = c[2], v3 = c[3];
            if (BIAS_MODE == 1) {
                float b0 = bias[col], b1 = bias[col + 1];
                v0 += b0; v1 += b1; v2 += b0; v3 += b1;
            } else if (BIAS_MODE == 2) {
                float br0 = bias[r0], br1 = bias[r1];
                v0 += br0; v1 += br0; v2 += br1; v3 += br1;
            }
            if (OUT_SPLIT) {
                bf16 h0 = __float2bfloat16(v0), h1 = __float2bfloat16(v1);
                bf16 h2 = __float2bfloat16(v2), h3 = __float2bfloat16(v3);
                bf16 l0 = __float2bfloat16(v0 - __bfloat162float(h0));
                bf16 l1 = __float2bfloat16(v1 - __bfloat162float(h1));
                bf16 l2 = __float2bfloat16(v2 - __bfloat162float(h2));
                bf16 l3 = __float2bfloat16(v3 - __bfloat162float(h3));
                *(uint32_t*)&Ch[(size_t)r0 * N + col] = pack2(h0, h1);
                *(uint32_t*)&Cl[(size_t)r0 * N + col] = pack2(l0, l1);
                *(uint32_t*)&Ch[(size_t)r1 * N + col] = pack2(h2, h3);
                *(uint32_t*)&Cl[(size_t)r1 * N + col] = pack2(l2, l3);
            } else {
                *(float2*)&Cf[(size_t)r0 * N + col] = make_float2(v0, v1);
                *(float2*)&Cf[(size_t)r1 * N + col] = make_float2(v2, v3);
            }
        }
    }
}

// ------------------------------------------------------------------
// row softmax: S fp32 -> P hi/lo bf16
// ------------------------------------------------------------------
__global__ __launch_bounds__(256) void softmax_rows(const float* __restrict__ S,
                                                    bf16* __restrict__ Ph, bf16* __restrict__ Pl)
{
    const int row = blockIdx.x;
    const float* p = S + (size_t)row * NTOK;
    const int tid = threadIdx.x;

    float vals[16];
    float mx = -INFINITY;
    #pragma unroll
    for (int i = 0; i < 16; i++) { vals[i] = p[tid + i * 256]; mx = fmaxf(mx, vals[i]); }

    __shared__ float red[8];
    #pragma unroll
    for (int o = 16; o; o >>= 1) mx = fmaxf(mx, __shfl_xor_sync(0xffffffffu, mx, o));
    if ((tid & 31) == 0) red[tid >> 5] = mx;
    __syncthreads();
    mx = red[0];
    #pragma unroll
    for (int i = 1; i < 8; i++) mx = fmaxf(mx, red[i]);
    __syncthreads();

    float s = 0.f;
    #pragma unroll
    for (int i = 0; i < 16; i++) { vals[i] = __expf(vals[i] - mx); s += vals[i]; }
    #pragma unroll
    for (int o = 16; o; o >>= 1) s += __shfl_xor_sync(0xffffffffu, s, o);
    if ((tid & 31) == 0) red[tid >> 5] = s;
    __syncthreads();
    s = red[0];
    #pragma unroll
    for (int i = 1; i < 8; i++) s += red[i];

    float inv = 1.f / s;
    #pragma unroll
    for (int i = 0; i < 16; i++) {
        float v = vals[i] * inv;
        bf16 h = __float2bfloat16(v);
        bf16 l = __float2bfloat16(v - __bfloat162float(h));
        size_t o = (size_t)row * NTOK + tid + i * 256;
        Ph[o] = h;
        Pl[o] = l;
    }
}

// ------------------------------------------------------------------
// residual + LayerNorm
// ------------------------------------------------------------------
__global__ __launch_bounds__(256) void residual_ln(const float* __restrict__ O, const float* __restrict__ X,
                                                   const float* __restrict__ gamma, const float* __restrict__ beta,
                                                   float* __restrict__ out)
{
    const int row = blockIdx.x;
    const int tid = threadIdx.x;
    const float* o = O + (size_t)row * DIM;
    const float* x = X + (size_t)row * DIM;

    float v[4];
    float s = 0.f;
    #pragma unroll
    for (int i = 0; i < 4; i++) {
        int c = tid + i * 256;
        v[i] = o[c] + x[c];
        s += v[i];
    }
    __shared__ float red[8];
    #pragma unroll
    for (int off = 16; off; off >>= 1) s += __shfl_xor_sync(0xffffffffu, s, off);
    if ((tid & 31) == 0) red[tid >> 5] = s;
    __syncthreads();
    s = red[0];
    #pragma unroll
    for (int i = 1; i < 8; i++) s += red[i];
    const float mu = s * (1.f / DIM);
    __syncthreads();

    float vs = 0.f;
    #pragma unroll
    for (int i = 0; i < 4; i++) { float d = v[i] - mu; vs += d * d; }
    #pragma unroll
    for (int off = 16; off; off >>= 1) vs += __shfl_xor_sync(0xffffffffu, vs, off);
    if ((tid & 31) == 0) red[tid >> 5] = vs;
    __syncthreads();
    vs = red[0];
    #pragma unroll
    for (int i = 1; i < 8; i++) vs += red[i];
    const float r = rsqrtf(vs * (1.f / DIM) + 1e-5f);

    #pragma unroll
    for (int i = 0; i < 4; i++) {
        int c = tid + i * 256;
        out[(size_t)row * DIM + c] = (v[i] - mu) * r * gamma[c] + beta[c];
    }
}

// ------------------------------------------------------------------
extern "C" void kernel_launch(void* const* d_in, const int* in_sizes, int n_in,
                              void* d_out, int out_size)
{
    const float* X     = (const float*)d_in[0];
    const float* Wk    = (const float*)d_in[1];
    const float* bk    = (const float*)d_in[2];
    const float* Wq    = (const float*)d_in[3];
    const float* bq    = (const float*)d_in[4];
    const float* Wv    = (const float*)d_in[5];
    const float* bv    = (const float*)d_in[6];
    const float* gamma = (const float*)d_in[7];
    const float* beta  = (const float*)d_in[8];
    float* out = (float*)d_out;

    bf16 *Xh, *Xl, *Wkth, *Wktl, *Wqth, *Wqtl, *Wvth, *Wvtl;
    bf16 *Kh, *Kl, *Qh, *Ql, *Vth, *Vtl, *Ph, *Pl;
    float *S, *O;
    cudaGetSymbolAddress((void**)&Xh, g_Xh);   cudaGetSymbolAddress((void**)&Xl, g_Xl);
    cudaGetSymbolAddress((void**)&Wkth, g_Wkt_h); cudaGetSymbolAddress((void**)&Wktl, g_Wkt_l);
    cudaGetSymbolAddress((void**)&Wqth, g_Wqt_h); cudaGetSymbolAddress((void**)&Wqtl, g_Wqt_l);
    cudaGetSymbolAddress((void**)&Wvth, g_Wvt_h); cudaGetSymbolAddress((void**)&Wvtl, g_Wvt_l);
    cudaGetSymbolAddress((void**)&Kh, g_Kh);   cudaGetSymbolAddress((void**)&Kl, g_Kl);
    cudaGetSymbolAddress((void**)&Qh, g_Qh);   cudaGetSymbolAddress((void**)&Ql, g_Ql);
    cudaGetSymbolAddress((void**)&Vth, g_Vth); cudaGetSymbolAddress((void**)&Vtl, g_Vtl);
    cudaGetSymbolAddress((void**)&Ph, g_Ph);   cudaGetSymbolAddress((void**)&Pl, g_Pl);
    cudaGetSymbolAddress((void**)&S, g_S);     cudaGetSymbolAddress((void**)&O, g_O);

    cudaFuncSetAttribute(gemm3_kernel<1, 1>, cudaFuncAttributeMaxDynamicSharedMemorySize, GEMM_SMEM);
    cudaFuncSetAttribute(gemm3_kernel<2, 1>, cudaFuncAttributeMaxDynamicSharedMemorySize, GEMM_SMEM);
    cudaFuncSetAttribute(gemm3_kernel<0, 0>, cudaFuncAttributeMaxDynamicSharedMemorySize, GEMM_SMEM);

    dim3 blk(256);

    // conversions
    split_kernel<<<(NTOK * DIM / 4 + 255) / 256, blk>>>(X, Xh, Xl, NTOK * DIM / 4);
    dim3 gT(DIM / 32, DIM / 32);
    transpose_split_kernel<<<gT, blk>>>(Wk, Wkth, Wktl);
    transpose_split_kernel<<<gT, blk>>>(Wq, Wqth, Wqtl);
    transpose_split_kernel<<<gT, blk>>>(Wv, Wvth, Wvtl);

    // K = X @ Wk + bk, Q = X @ Wq + bq  (M=4096, N=1024, K=1024)
    dim3 gKQ(DIM / BN, NTOK / BM);
    gemm3_kernel<1, 1><<<gKQ, blk, GEMM_SMEM>>>(Xh, Xl, Wkth, Wktl, bk, nullptr, Kh, Kl, DIM, DIM);
    gemm3_kernel<1, 1><<<gKQ, blk, GEMM_SMEM>>>(Xh, Xl, Wqth, Wqtl, bq, nullptr, Qh, Ql, DIM, DIM);

    // Vt[d][t] = sum_k Wv[k][d] X[t][k] + bv[d]  (M=1024, N=4096, K=1024, per-row bias)
    dim3 gV(NTOK / BN, DIM / BM);
    gemm3_kernel<2, 1><<<gV, blk, GEMM_SMEM>>>(Wvth, Wvtl, Xh, Xl, bv, nullptr, Vth, Vtl, NTOK, DIM);

    // scores: S = K @ Q^T (M=4096, N=4096, K=1024), fp32 out
    dim3 gS(NTOK / BN, NTOK / BM);
    gemm3_kernel<0, 0><<<gS, blk, GEMM_SMEM>>>(Kh, Kl, Qh, Ql, nullptr, S, nullptr, nullptr, NTOK, DIM);

    // softmax rows -> P hi/lo
    softmax_rows<<<NTOK, blk>>>(S, Ph, Pl);

    // O = P @ V  (M=4096, N=1024, K=4096)
    dim3 gO(DIM / BN, NTOK / BM);
    gemm3_kernel<0, 0><<<gO, blk, GEMM_SMEM>>>(Ph, Pl, Vth, Vtl, nullptr, O, nullptr, nullptr, DIM, NTOK);

    // residual + LN
    residual_ln<<<NTOK, blk>>>(O, X, gamma, beta, out);
}